// round 2
// baseline (speedup 1.0000x reference)
#include <cuda_runtime.h>

// waspGridSpatialIntegral: out[:,0,:,:] = inclusive cumsum over width  (contiguous)
//                          out[:,1,:,:] = inclusive cumsum over height (stride-W)
// B=64, W=512, fp32. Memory-bound: 128 MiB read + 128 MiB write.
//
// Single fused kernel. Blocks [0, YB) do the y-scan (long serial chains,
// scheduled first so their latency hides under the x-scan's bandwidth).
// Blocks [YB, YB+XB) do the x-scan (one warp per row, float4 traffic).

#define W 512
#define BATCH 64

#define YB ((BATCH * W) / 256)        // 128 y-scan blocks (1 thread / column)
#define XB ((BATCH * W * 32) / 256)   // 4096 x-scan blocks (1 warp / row)

__global__ __launch_bounds__(256) void wasp_integral_kernel(
    const float* __restrict__ in, float* __restrict__ out)
{
    if (blockIdx.x < YB) {
        // ----------------- y-scan: one thread per (batch, column) -----------
        const int idx = blockIdx.x * 256 + threadIdx.x;   // [0, BATCH*W)
        const int b = idx >> 9;
        const int x = idx & (W - 1);

        const size_t plane = (size_t)(b * 2 + 1) * W * W + x;   // channel 1
        const float* src = in + plane;
        float*       dst = out + plane;

        float sum = 0.0f;
        // MLP-32 batches: 32 independent LDGs front-batched, then the serial
        // accumulate + store chain consumes them.
        for (int t = 0; t < W / 32; t++) {
            float v[32];
            #pragma unroll
            for (int i = 0; i < 32; i++)
                v[i] = src[(size_t)(t * 32 + i) * W];
            #pragma unroll
            for (int i = 0; i < 32; i++) {
                sum += v[i];
                dst[(size_t)(t * 32 + i) * W] = sum;
            }
        }
    } else {
        // ----------------- x-scan: one warp per row -------------------------
        const int bx    = blockIdx.x - YB;
        const int gwarp = (bx * 256 + threadIdx.x) >> 5;  // [0, BATCH*W)
        const int lane  = threadIdx.x & 31;

        const int b = gwarp >> 9;
        const int y = gwarp & (W - 1);

        const size_t plane = (size_t)(b * 2) * W * W + (size_t)y * W;  // channel 0
        const float4* src = reinterpret_cast<const float4*>(in + plane) + lane * 4;
        float4*       dst = reinterpret_cast<float4*>(out + plane) + lane * 4;

        float4 a0 = src[0];
        float4 a1 = src[1];
        float4 a2 = src[2];
        float4 a3 = src[3];

        float v[16];
        v[0]=a0.x;  v[1]=a0.y;  v[2]=a0.z;  v[3]=a0.w;
        v[4]=a1.x;  v[5]=a1.y;  v[6]=a1.z;  v[7]=a1.w;
        v[8]=a2.x;  v[9]=a2.y;  v[10]=a2.z; v[11]=a2.w;
        v[12]=a3.x; v[13]=a3.y; v[14]=a3.z; v[15]=a3.w;

        // serial inclusive scan of the 16-element chunk
        #pragma unroll
        for (int i = 1; i < 16; i++) v[i] += v[i - 1];

        // warp shuffle exclusive scan of per-lane totals
        float total = v[15];
        float incl  = total;
        #pragma unroll
        for (int d = 1; d < 32; d <<= 1) {
            float n = __shfl_up_sync(0xFFFFFFFFu, incl, d);
            if (lane >= d) incl += n;
        }
        const float excl = incl - total;

        #pragma unroll
        for (int i = 0; i < 16; i++) v[i] += excl;

        dst[0] = make_float4(v[0],  v[1],  v[2],  v[3]);
        dst[1] = make_float4(v[4],  v[5],  v[6],  v[7]);
        dst[2] = make_float4(v[8],  v[9],  v[10], v[11]);
        dst[3] = make_float4(v[12], v[13], v[14], v[15]);
    }
}

extern "C" void kernel_launch(void* const* d_in, const int* in_sizes, int n_in,
                              void* d_out, int out_size)
{
    const float* in  = (const float*)d_in[0];
    float*       out = (float*)d_out;
    wasp_integral_kernel<<<YB + XB, 256>>>(in, out);
}